// round 13
// baseline (speedup 1.0000x reference)
#include <cuda_runtime.h>
#include <cuda_fp16.h>
#include <cstdint>

#define TQ   2048
#define DDIM 1024
#define FDIM 4096
#define NEXP 8
#define MAXT 24          // 128-row tiles: sum ceil(n_e/128) <= 16 + 7 = 23

// router stage: A 16KB + Bhi 4KB + Blo 4KB
#define RSTAGE 24576
#define RSMEM (2 * RSTAGE + 1024)
// expert stage (BK=128): A 32KB (128 rows x 256B) + Bhi 16KB (128 k x 128B)
#define ESTAGE 49152
#define ESMEM (2 * ESTAGE + 256)

// ---------------- scratch globals ------------------------------------------
__device__ float  g_h[(size_t)TQ * DDIM];
__device__ __half g_seqh[(size_t)TQ * DDIM];
__device__ __half g_seql[(size_t)TQ * DDIM];
__device__ __half g_hidh[(size_t)TQ * FDIM];
__device__ int   g_expert[TQ];
__device__ int   g_counts[NEXP];
__device__ int   g_offsets[NEXP];
__device__ int   g_cursor[NEXP];
__device__ int   g_perm[TQ];
__device__ int   g_t1e[MAXT], g_t1r[MAXT], g_nt1;
__device__ int   g_done;

// ---------------- helpers ---------------------------------------------------
__device__ __forceinline__ uint32_t smem_u32(const void* p) {
    uint32_t a;
    asm("{ .reg .u64 t; cvta.to.shared.u64 t, %1; cvt.u32.u64 %0, t; }" : "=r"(a) : "l"(p));
    return a;
}
// 128B-period swizzle: XOR bits[4:6] ^= bits[7:9]
#define SWZ(o) ((o) ^ (((o) >> 3) & 0x70))
// 256B-period swizzle: XOR bits[4:6] ^= bits[8:10]
#define SWZB(o) ((o) ^ (((o) >> 4) & 0x70))

__device__ __forceinline__ void sts128(uint32_t a, uint32_t x, uint32_t y, uint32_t z, uint32_t w) {
    asm volatile("st.shared.v4.b32 [%0], {%1,%2,%3,%4};" :: "r"(a), "r"(x), "r"(y), "r"(z), "r"(w));
}
__device__ __forceinline__ void cp16(uint32_t dst, const void* src) {
    asm volatile("cp.async.cg.shared.global [%0], [%1], 16;" :: "r"(dst), "l"(src) : "memory");
}
__device__ __forceinline__ void cp_commit() {
    asm volatile("cp.async.commit_group;" ::: "memory");
}
__device__ __forceinline__ void cp_wait0() {
    asm volatile("cp.async.wait_group 0;" ::: "memory");
}
__device__ __forceinline__ void ldsm4(uint32_t (&r)[4], uint32_t addr) {
    asm volatile("ldmatrix.sync.aligned.m8n8.x4.shared.b16 {%0,%1,%2,%3}, [%4];"
                 : "=r"(r[0]), "=r"(r[1]), "=r"(r[2]), "=r"(r[3]) : "r"(addr));
}
__device__ __forceinline__ void ldsm4t(uint32_t (&r)[4], uint32_t addr) {
    asm volatile("ldmatrix.sync.aligned.m8n8.x4.trans.shared.b16 {%0,%1,%2,%3}, [%4];"
                 : "=r"(r[0]), "=r"(r[1]), "=r"(r[2]), "=r"(r[3]) : "r"(addr));
}
__device__ __forceinline__ void mma_f32(float (&d)[4], const uint32_t (&a)[4],
                                        uint32_t b0, uint32_t b1) {
    asm volatile("mma.sync.aligned.m16n8k16.row.col.f32.f16.f16.f32 "
                 "{%0,%1,%2,%3}, {%4,%5,%6,%7}, {%8,%9}, {%0,%1,%2,%3};"
                 : "+f"(d[0]), "+f"(d[1]), "+f"(d[2]), "+f"(d[3])
                 : "r"(a[0]), "r"(a[1]), "r"(a[2]), "r"(a[3]), "r"(b0), "r"(b1));
}
__device__ __forceinline__ void mma_f16(uint32_t (&d)[2], const uint32_t (&a)[4],
                                        uint32_t b0, uint32_t b1) {
    asm volatile("mma.sync.aligned.m16n8k16.row.col.f16.f16.f16.f16 "
                 "{%0,%1}, {%2,%3,%4,%5}, {%6,%7}, {%0,%1};"
                 : "+r"(d[0]), "+r"(d[1])
                 : "r"(a[0]), "r"(a[1]), "r"(a[2]), "r"(a[3]), "r"(b0), "r"(b1));
}
__device__ __forceinline__ void split2h(float x, float y, uint32_t& hi, uint32_t& lo) {
    __half2 h = __float22half2_rn(make_float2(x, y));
    float2 hf = __half22float2(h);
    __half2 l = __float22half2_rn(make_float2(x - hf.x, y - hf.y));
    hi = *(uint32_t*)&h; lo = *(uint32_t*)&l;
}
__device__ __forceinline__ uint32_t cvt2h(float x, float y) {
    __half2 h = __float22half2_rn(make_float2(x, y));
    return *(uint32_t*)&h;
}

// ---------------- small kernels --------------------------------------------
// seq fp32 -> fp16 hi/lo (once); block 0 also resets counters + done flag
__global__ void k_cvtA(const float* __restrict__ seq) {
    if (blockIdx.x == 0 && threadIdx.x < NEXP) {
        g_counts[threadIdx.x] = 0; g_cursor[threadIdx.x] = 0;
        if (threadIdx.x == 0) g_done = 0;
    }
    size_t i = ((size_t)blockIdx.x * 256 + threadIdx.x) * 4;
    float4 v = *(const float4*)(seq + i);
    uint32_t h0, h1, l0, l1;
    split2h(v.x, v.y, h0, l0);
    split2h(v.z, v.w, h1, l1);
    *(uint2*)(g_seqh + i) = make_uint2(h0, h1);
    *(uint2*)(g_seql + i) = make_uint2(l0, l1);
}

// Router stage 2 + argmax + histogram; LAST block builds tile list + scatters.
__global__ void k_router2(const float* __restrict__ W2, const float* __restrict__ b2) {
    int t = blockIdx.x;
    const float* hr = g_h + (size_t)t * DDIM;
    float p[NEXP];
#pragma unroll
    for (int e = 0; e < NEXP; e++) p[e] = 0.f;
    for (int d = threadIdx.x; d < DDIM; d += 256) {
        float hv = hr[d];
        const float* w = W2 + (size_t)d * NEXP;
#pragma unroll
        for (int e = 0; e < NEXP; e++) p[e] = fmaf(hv, w[e], p[e]);
    }
    __shared__ float sm[8][NEXP];
    __shared__ int s_last;
#pragma unroll
    for (int e = 0; e < NEXP; e++) {
        float v = p[e];
#pragma unroll
        for (int o = 16; o > 0; o >>= 1) v += __shfl_down_sync(0xffffffffu, v, o);
        if ((threadIdx.x & 31) == 0) sm[threadIdx.x >> 5][e] = v;
    }
    __syncthreads();
    if (threadIdx.x == 0) {
        float best = -1e30f; int bi = 0;
#pragma unroll
        for (int e = 0; e < NEXP; e++) {
            float v = b2[e];
#pragma unroll
            for (int w = 0; w < 8; w++) v += sm[w][e];
            if (v > best) { best = v; bi = e; }   // strict '>' == first-max
        }
        g_expert[t] = bi;
        atomicAdd(&g_counts[bi], 1);
        __threadfence();
        int d = atomicAdd(&g_done, 1);
        s_last = (d == TQ - 1);
    }
    __syncthreads();
    if (s_last) {
        __threadfence();
        if (threadIdx.x == 0) {
            int off = 0, n1 = 0;
            for (int e = 0; e < NEXP; e++) {
                int c = g_counts[e];
                g_offsets[e] = off; off += c;
                for (int r = 0; r < c; r += 128) { g_t1e[n1] = e; g_t1r[n1] = r; n1++; }
            }
            g_nt1 = n1;
        }
        __syncthreads();
        for (int t2 = threadIdx.x; t2 < TQ; t2 += 256) {
            int e = g_expert[t2];
            int pos = g_offsets[e] + atomicAdd(&g_cursor[e], 1);
            g_perm[pos] = t2;
        }
    }
}

// ============ ROUTER GEMM: 3-MMA fp16-split, BK=32 (argmax-critical) ========
__global__ void __launch_bounds__(256, 2)
k_rt(const float* __restrict__ Bw, const float* __restrict__ bias, int N, int K)
{
    extern __shared__ char rawsm[];
    const uint32_t sb = (smem_u32(rawsm) + 1023u) & ~1023u;

    const int tid  = threadIdx.x;
    const int lane = tid & 31;
    const int wid  = tid >> 5;
    const int m_off = (wid >> 1) * 32;
    const int nw    = (wid & 1) * 32;
    const int m0 = blockIdx.x * 128;
    const int n0 = blockIdx.y * 64;

    const int arw = tid >> 1, ah_ = tid & 1;
    const __half* ah_src = g_seqh + (size_t)(m0 + arw) * K;
    const __half* al_src = g_seql + (size_t)(m0 + arw) * K;
    const uint32_t a_hi_dst0 = SWZ((uint32_t)arw * 128 + ah_ * 32);
    const uint32_t a_hi_dst1 = SWZ((uint32_t)arw * 128 + ah_ * 32 + 16);
    const uint32_t a_lo_dst0 = SWZ((uint32_t)arw * 128 + 64 + ah_ * 32);
    const uint32_t a_lo_dst1 = SWZ((uint32_t)arw * 128 + 64 + ah_ * 32 + 16);

    const int bkr_ = tid >> 3, bc8 = (tid & 7) * 8;
    const float* brow = Bw + (size_t)bkr_ * N + n0 + bc8;
    const uint32_t b_sts = SWZ((uint32_t)bkr_ * 128 + bc8 * 2);

    float acc[2][4][4];
    uint32_t corr[2][4][2];
#pragma unroll
    for (int i = 0; i < 2; i++)
#pragma unroll
        for (int j = 0; j < 4; j++) {
#pragma unroll
            for (int q = 0; q < 4; q++) acc[i][j][q] = 0.f;
            corr[i][j][0] = 0u; corr[i][j][1] = 0u;
        }

    const int nch = K >> 5;
    float4 lb[2];

    auto issue_A = [&](int ch, int s) {
        const uint32_t ab = sb + s * RSTAGE;
        const __half* ph = ah_src + ch * 32 + ah_ * 16;
        const __half* pl = al_src + ch * 32 + ah_ * 16;
        cp16(ab + a_hi_dst0, ph);
        cp16(ab + a_hi_dst1, ph + 8);
        cp16(ab + a_lo_dst0, pl);
        cp16(ab + a_lo_dst1, pl + 8);
    };
    auto load_B = [&](int ch) {
        const float* bp = brow + (size_t)(ch * 32) * N;
        lb[0] = *(const float4*)bp;
        lb[1] = *(const float4*)(bp + 4);
    };
    auto store_B = [&](int s) {
        const uint32_t bh = sb + s * RSTAGE + 16384;
        const uint32_t bl = bh + 4096;
        uint32_t h0, h1, h2, h3, l0, l1, l2, l3;
        split2h(lb[0].x, lb[0].y, h0, l0);
        split2h(lb[0].z, lb[0].w, h1, l1);
        split2h(lb[1].x, lb[1].y, h2, l2);
        split2h(lb[1].z, lb[1].w, h3, l3);
        sts128(bh + b_sts, h0, h1, h2, h3);
        sts128(bl + b_sts, l0, l1, l2, l3);
    };
    auto compute = [&](int s) {
        const uint32_t ab = sb + s * RSTAGE;
        const uint32_t bhb = ab + 16384, blb = ab + 20480;
#pragma unroll
        for (int ks = 0; ks < 2; ks++) {
            uint32_t ahf[2][4], alf[2][4];
            const uint32_t acb = (uint32_t)ks * 32 + (lane >> 4) * 16;
            const int arl = lane & 15;
#pragma unroll
            for (int mf = 0; mf < 2; mf++) {
                uint32_t rb = (uint32_t)(m_off + mf * 16 + arl) * 128;
                ldsm4(ahf[mf], ab + SWZ(rb + acb));
                ldsm4(alf[mf], ab + SWZ(rb + 64 + acb));
            }
            uint32_t bhf[4][2], blf[4][2];
            const uint32_t bkr = (uint32_t)(ks * 16 + (lane & 15)) * 128;
#pragma unroll
            for (int g = 0; g < 2; g++) {
                uint32_t cb = (uint32_t)(nw + g * 16 + 8 * (lane >> 4)) * 2;
                uint32_t r[4];
                ldsm4t(r, bhb + SWZ(bkr + cb));
                bhf[2 * g][0] = r[0]; bhf[2 * g][1] = r[1];
                bhf[2 * g + 1][0] = r[2]; bhf[2 * g + 1][1] = r[3];
                ldsm4t(r, blb + SWZ(bkr + cb));
                blf[2 * g][0] = r[0]; blf[2 * g][1] = r[1];
                blf[2 * g + 1][0] = r[2]; blf[2 * g + 1][1] = r[3];
            }
#pragma unroll
            for (int mf = 0; mf < 2; mf++)
#pragma unroll
                for (int nf = 0; nf < 4; nf++) {
                    mma_f32(acc[mf][nf], ahf[mf], bhf[nf][0], bhf[nf][1]);
                    mma_f16(corr[mf][nf], alf[mf], bhf[nf][0], bhf[nf][1]);
                    mma_f16(corr[mf][nf], ahf[mf], blf[nf][0], blf[nf][1]);
                }
        }
    };

    issue_A(0, 0);
    cp_commit();
    load_B(0);
    cp_wait0();
    store_B(0);
    __syncthreads();
    for (int ch = 0; ch < nch; ch++) {
        int s = ch & 1;
        if (ch + 1 < nch) {
            issue_A(ch + 1, s ^ 1);
            cp_commit();
            load_B(ch + 1);
        }
        compute(s);
        if (ch + 1 < nch) store_B(s ^ 1);
        cp_wait0();
        __syncthreads();
    }

    float2 bias2[4];
#pragma unroll
    for (int nf = 0; nf < 4; nf++)
        bias2[nf] = *(const float2*)(bias + n0 + nw + nf * 8 + 2 * (lane & 3));

#pragma unroll
    for (int mf = 0; mf < 2; mf++) {
        int rl = m_off + mf * 16 + (lane >> 2);
#pragma unroll
        for (int half = 0; half < 2; half++) {
            int m = rl + half * 8;
            float* dp = g_h + (size_t)(m0 + m) * N;
#pragma unroll
            for (int nf = 0; nf < 4; nf++) {
                int col = n0 + nw + nf * 8 + 2 * (lane & 3);
                float2 cf = __half22float2(*(__half2*)&corr[mf][nf][half]);
                float x = fmaxf(acc[mf][nf][half * 2 + 0] + cf.x + bias2[nf].x, 0.f);
                float y = fmaxf(acc[mf][nf][half * 2 + 1] + cf.y + bias2[nf].y, 0.f);
                *(float2*)(dp + col) = make_float2(x, y);
            }
        }
    }
}

// ============ EXPERT GEMM: 1-MMA, tile 128x64, BK=128 =======================
// 8 warps: warp tile 32x32 (4 m-warps x 2 n-warps). B fp32 loaded in 2 batches
// interleaved with the 2 compute halves (halves chunk/barrier count vs BK=64).
// MODE 1: g_hidh[perm] = relu(gather(g_seqh) @ ew1[e] + eb1[e])
// MODE 2: out[perm[r]] = g_hidh @ ew2[e] + eb2[e]
template <int MODE>
__global__ void __launch_bounds__(256, 2)
k_ex(const float* __restrict__ Bw, const float* __restrict__ bias,
     float* __restrict__ C, int N, int K)
{
    extern __shared__ char rawsm[];
    const uint32_t sb = (smem_u32(rawsm) + 255u) & ~255u;

    const int tid  = threadIdx.x;
    const int lane = tid & 31;
    const int wid  = tid >> 5;
    const int m_off = (wid >> 1) * 32;
    const int nw    = (wid & 1) * 32;

    int mt = blockIdx.x;
    if (mt >= g_nt1) return;
    const int e = g_t1e[mt], row0 = g_t1r[mt];
    const int cnt = g_counts[e], goff = g_offsets[e];
    const float* Bp = Bw + (size_t)e * K * N;
    const float* biasp = bias + (size_t)e * N;
    const int n0 = blockIdx.y * 64;

    // ---- A loader: row = tid>>1 (0..127), half = tid&1 (64 halfs = 128B)
    const int arw = tid >> 1, ah_ = tid & 1;
    const __half* ah_src;
    {
        int rr = row0 + arw;
        int src = (rr < cnt ? rr : cnt - 1);
        if (MODE == 1) ah_src = g_seqh + (size_t)g_perm[goff + src] * K;
        else           ah_src = g_hidh + (size_t)(goff + src) * K;
    }
    uint32_t a_dst[8];
#pragma unroll
    for (int i = 0; i < 8; i++)
        a_dst[i] = SWZB((uint32_t)arw * 256 + ah_ * 128 + i * 16);

    // ---- B loader: krow = tid>>1 (0..127), half = tid&1 -> 32 floats (2 batches)
    const int bkrw = tid >> 1, bh_ = tid & 1;
    const float* brow = Bp + (size_t)bkrw * N + n0 + bh_ * 32;
    const uint32_t b_sts_base = (uint32_t)bkrw * 128 + bh_ * 64;

    float acc[2][4][4];
#pragma unroll
    for (int i = 0; i < 2; i++)
#pragma unroll
        for (int j = 0; j < 4; j++)
#pragma unroll
            for (int q = 0; q < 4; q++) acc[i][j][q] = 0.f;

    const int nch = K >> 7;
    float4 lb[4];

    auto issue_A = [&](int ch, int s) {
        const uint32_t ab = sb + s * ESTAGE;
        const __half* ph = ah_src + ch * 128 + ah_ * 64;
#pragma unroll
        for (int i = 0; i < 8; i++) cp16(ab + a_dst[i], ph + 8 * i);
    };
    auto load_B = [&](int ch, int b) {
        const float* bp = brow + (size_t)(ch * 128) * N + b * 16;
#pragma unroll
        for (int i = 0; i < 4; i++) lb[i] = *(const float4*)(bp + 4 * i);
    };
    auto store_B = [&](int s, int b) {
        const uint32_t bh = sb + s * ESTAGE + 32768;
        uint32_t h[8];
#pragma unroll
        for (int i = 0; i < 4; i++) {
            h[2 * i]     = cvt2h(lb[i].x, lb[i].y);
            h[2 * i + 1] = cvt2h(lb[i].z, lb[i].w);
        }
        uint32_t o = b_sts_base + b * 32;
        sts128(bh + SWZ(o), h[0], h[1], h[2], h[3]);
        sts128(bh + SWZ(o + 16), h[4], h[5], h[6], h[7]);
    };
    auto compute_half = [&](int s, int hh) {
        const uint32_t ab = sb + s * ESTAGE;
        const uint32_t bhb = ab + 32768;
#pragma unroll
        for (int kk = 0; kk < 4; kk++) {
            int ks = hh * 4 + kk;
            uint32_t ahf[2][4];
            const uint32_t acb = (uint32_t)ks * 32 + (lane >> 4) * 16;
            const int arl = lane & 15;
#pragma unroll
            for (int mf = 0; mf < 2; mf++)
                ldsm4(ahf[mf], ab + SWZB((uint32_t)(m_off + mf * 16 + arl) * 256 + acb));
            uint32_t bhf[4][2];
            const uint32_t bkr = (uint32_t)(ks * 16 + (lane & 15)) * 128;
#pragma unroll
            for (int g = 0; g < 2; g++) {
                uint32_t cb = (uint32_t)(nw + g * 16 + 8 * (lane >> 4)) * 2;
                uint32_t r[4];
                ldsm4t(r, bhb + SWZ(bkr + cb));
                bhf[2 * g][0] = r[0]; bhf[2 * g][1] = r[1];
                bhf[2 * g + 1][0] = r[2]; bhf[2 * g + 1][1] = r[3];
            }
#pragma unroll
            for (int mf = 0; mf < 2; mf++)
#pragma unroll
                for (int nf = 0; nf < 4; nf++)
                    mma_f32(acc[mf][nf], ahf[mf], bhf[nf][0], bhf[nf][1]);
        }
    };

    // prologue: stage 0
    issue_A(0, 0);
    cp_commit();
    load_B(0, 0);
    store_B(0, 0);
    load_B(0, 1);
    store_B(0, 1);
    cp_wait0();
    __syncthreads();
    for (int ch = 0; ch < nch; ch++) {
        int s = ch & 1;
        if (ch + 1 < nch) {
            issue_A(ch + 1, s ^ 1);
            cp_commit();
            load_B(ch + 1, 0);
        }
        compute_half(s, 0);
        if (ch + 1 < nch) {
            store_B(s ^ 1, 0);
            load_B(ch + 1, 1);
        }
        compute_half(s, 1);
        if (ch + 1 < nch) store_B(s ^ 1, 1);
        cp_wait0();
        __syncthreads();
    }

    float2 bias2[4];
#pragma unroll
    for (int nf = 0; nf < 4; nf++)
        bias2[nf] = *(const float2*)(biasp + n0 + nw + nf * 8 + 2 * (lane & 3));

#pragma unroll
    for (int mf = 0; mf < 2; mf++) {
        int rl = m_off + mf * 16 + (lane >> 2);
#pragma unroll
        for (int half = 0; half < 2; half++) {
            int m = rl + half * 8;
            int rr = row0 + m;
            if (rr < cnt) {
                if (MODE == 1) {
                    size_t rowbase = (size_t)(goff + rr) * N;
#pragma unroll
                    for (int nf = 0; nf < 4; nf++) {
                        int col = n0 + nw + nf * 8 + 2 * (lane & 3);
                        float x = fmaxf(acc[mf][nf][half * 2 + 0] + bias2[nf].x, 0.f);
                        float y = fmaxf(acc[mf][nf][half * 2 + 1] + bias2[nf].y, 0.f);
                        *(uint32_t*)(g_hidh + rowbase + col) = cvt2h(x, y);
                    }
                } else {
                    float* dp = C + (size_t)g_perm[goff + rr] * N;
#pragma unroll
                    for (int nf = 0; nf < 4; nf++) {
                        int col = n0 + nw + nf * 8 + 2 * (lane & 3);
                        float x = acc[mf][nf][half * 2 + 0] + bias2[nf].x;
                        float y = acc[mf][nf][half * 2 + 1] + bias2[nf].y;
                        *(float2*)(dp + col) = make_float2(x, y);
                    }
                }
            }
        }
    }
}

// ---------------- launch ----------------------------------------------------
extern "C" void kernel_launch(void* const* d_in, const int* in_sizes, int n_in,
                              void* d_out, int out_size) {
    const float* seq = (const float*)d_in[0];
    const float* rw1 = (const float*)d_in[1];
    const float* rb1 = (const float*)d_in[2];
    const float* rw2 = (const float*)d_in[3];
    const float* rb2 = (const float*)d_in[4];
    const float* ew1 = (const float*)d_in[5];
    const float* eb1 = (const float*)d_in[6];
    const float* ew2 = (const float*)d_in[7];
    const float* eb2 = (const float*)d_in[8];
    float* out = (float*)d_out;

    cudaFuncSetAttribute((const void*)k_rt,    cudaFuncAttributeMaxDynamicSharedMemorySize, RSMEM);
    cudaFuncSetAttribute((const void*)k_ex<1>, cudaFuncAttributeMaxDynamicSharedMemorySize, ESMEM);
    cudaFuncSetAttribute((const void*)k_ex<2>, cudaFuncAttributeMaxDynamicSharedMemorySize, ESMEM);

    // Launch #4 = k_ex<1> (profiler window).
    k_cvtA<<<TQ * DDIM / 1024, 256>>>(seq);
    // Router layer 1 (3-MMA split): h = relu(X @ rw1 + rb1)
    k_rt<<<dim3(TQ / 128, DDIM / 64), 256, RSMEM>>>(rw1, rb1, DDIM, DDIM);
    // Router layer 2 + argmax + histogram + (last block) tile list + scatter
    k_router2<<<TQ, 256>>>(rw2, rb2);
    // Expert FFN layer 1 (128x64 tiles, BK=128): hid = relu(X_e @ ew1[e] + eb1[e])
    k_ex<1><<<dim3(MAXT, FDIM / 64), 256, ESMEM>>>(ew1, eb1, nullptr, FDIM, DDIM);
    // Expert FFN layer 2 (128x64 tiles, BK=128): out = hid @ ew2[e] + eb2[e]
    k_ex<2><<<dim3(MAXT, DDIM / 64), 256, ESMEM>>>(ew2, eb2, out, DDIM, FDIM);
}

// round 14
// speedup vs baseline: 2.2757x; 2.2757x over previous
#include <cuda_runtime.h>
#include <cuda_fp16.h>
#include <cstdint>

#define TQ   2048
#define DDIM 1024
#define FDIM 4096
#define NEXP 8
#define MAXT 24          // 128-row tiles: sum ceil(n_e/128) <= 16 + 7 = 23

// router stage: A 16KB + Bhi 4KB + Blo 4KB
#define RSTAGE 24576
#define RSMEM (2 * RSTAGE + 1024)
// expert stage: A-hi 16KB (128 rows x 64 halfs) + Bhi 8KB
#define ESTAGE 24576
#define ESMEM (2 * ESTAGE + 1024)

// ---------------- scratch globals ------------------------------------------
__device__ float  g_h[(size_t)TQ * DDIM];
__device__ __half g_seqh[(size_t)TQ * DDIM];
__device__ __half g_seql[(size_t)TQ * DDIM];
__device__ __half g_hidh[(size_t)TQ * FDIM];
__device__ int   g_expert[TQ];
__device__ int   g_counts[NEXP];
__device__ int   g_offsets[NEXP];
__device__ int   g_cursor[NEXP];
__device__ int   g_perm[TQ];
__device__ int   g_t1e[MAXT], g_t1r[MAXT], g_nt1;
__device__ int   g_done;

// ---------------- helpers ---------------------------------------------------
__device__ __forceinline__ uint32_t smem_u32(const void* p) {
    uint32_t a;
    asm("{ .reg .u64 t; cvta.to.shared.u64 t, %1; cvt.u32.u64 %0, t; }" : "=r"(a) : "l"(p));
    return a;
}
// 128B-period swizzle: XOR bits[4:6] ^= bits[7:9]
#define SWZ(o) ((o) ^ (((o) >> 3) & 0x70))

__device__ __forceinline__ void sts128(uint32_t a, uint32_t x, uint32_t y, uint32_t z, uint32_t w) {
    asm volatile("st.shared.v4.b32 [%0], {%1,%2,%3,%4};" :: "r"(a), "r"(x), "r"(y), "r"(z), "r"(w));
}
__device__ __forceinline__ void cp16(uint32_t dst, const void* src) {
    asm volatile("cp.async.cg.shared.global [%0], [%1], 16;" :: "r"(dst), "l"(src) : "memory");
}
__device__ __forceinline__ void cp_commit() {
    asm volatile("cp.async.commit_group;" ::: "memory");
}
__device__ __forceinline__ void cp_wait0() {
    asm volatile("cp.async.wait_group 0;" ::: "memory");
}
__device__ __forceinline__ void ldsm4(uint32_t (&r)[4], uint32_t addr) {
    asm volatile("ldmatrix.sync.aligned.m8n8.x4.shared.b16 {%0,%1,%2,%3}, [%4];"
                 : "=r"(r[0]), "=r"(r[1]), "=r"(r[2]), "=r"(r[3]) : "r"(addr));
}
__device__ __forceinline__ void ldsm4t(uint32_t (&r)[4], uint32_t addr) {
    asm volatile("ldmatrix.sync.aligned.m8n8.x4.trans.shared.b16 {%0,%1,%2,%3}, [%4];"
                 : "=r"(r[0]), "=r"(r[1]), "=r"(r[2]), "=r"(r[3]) : "r"(addr));
}
__device__ __forceinline__ void mma_f32(float (&d)[4], const uint32_t (&a)[4],
                                        uint32_t b0, uint32_t b1) {
    asm volatile("mma.sync.aligned.m16n8k16.row.col.f32.f16.f16.f32 "
                 "{%0,%1,%2,%3}, {%4,%5,%6,%7}, {%8,%9}, {%0,%1,%2,%3};"
                 : "+f"(d[0]), "+f"(d[1]), "+f"(d[2]), "+f"(d[3])
                 : "r"(a[0]), "r"(a[1]), "r"(a[2]), "r"(a[3]), "r"(b0), "r"(b1));
}
__device__ __forceinline__ void mma_f16(uint32_t (&d)[2], const uint32_t (&a)[4],
                                        uint32_t b0, uint32_t b1) {
    asm volatile("mma.sync.aligned.m16n8k16.row.col.f16.f16.f16.f16 "
                 "{%0,%1}, {%2,%3,%4,%5}, {%6,%7}, {%0,%1};"
                 : "+r"(d[0]), "+r"(d[1])
                 : "r"(a[0]), "r"(a[1]), "r"(a[2]), "r"(a[3]), "r"(b0), "r"(b1));
}
__device__ __forceinline__ void split2h(float x, float y, uint32_t& hi, uint32_t& lo) {
    __half2 h = __float22half2_rn(make_float2(x, y));
    float2 hf = __half22float2(h);
    __half2 l = __float22half2_rn(make_float2(x - hf.x, y - hf.y));
    hi = *(uint32_t*)&h; lo = *(uint32_t*)&l;
}
__device__ __forceinline__ uint32_t cvt2h(float x, float y) {
    __half2 h = __float22half2_rn(make_float2(x, y));
    return *(uint32_t*)&h;
}

// ---------------- small kernels --------------------------------------------
// seq fp32 -> fp16 hi/lo (once); block 0 also resets counters + done flag
__global__ void k_cvtA(const float* __restrict__ seq) {
    if (blockIdx.x == 0 && threadIdx.x < NEXP) {
        g_counts[threadIdx.x] = 0; g_cursor[threadIdx.x] = 0;
        if (threadIdx.x == 0) g_done = 0;
    }
    size_t i = ((size_t)blockIdx.x * 256 + threadIdx.x) * 4;
    float4 v = *(const float4*)(seq + i);
    uint32_t h0, h1, l0, l1;
    split2h(v.x, v.y, h0, l0);
    split2h(v.z, v.w, h1, l1);
    *(uint2*)(g_seqh + i) = make_uint2(h0, h1);
    *(uint2*)(g_seql + i) = make_uint2(l0, l1);
}

// zero d_out (needed by the k-split atomicAdd epilogue of expert layer 2)
__global__ void k_zero(float* __restrict__ out) {
    size_t i = ((size_t)blockIdx.x * 256 + threadIdx.x) * 4;
    *(float4*)(out + i) = make_float4(0.f, 0.f, 0.f, 0.f);
}

// Router stage 2 + argmax + histogram; LAST block builds tile list + scatters.
__global__ void k_router2(const float* __restrict__ W2, const float* __restrict__ b2) {
    int t = blockIdx.x;
    const float* hr = g_h + (size_t)t * DDIM;
    float p[NEXP];
#pragma unroll
    for (int e = 0; e < NEXP; e++) p[e] = 0.f;
    for (int d = threadIdx.x; d < DDIM; d += 256) {
        float hv = hr[d];
        const float* w = W2 + (size_t)d * NEXP;
#pragma unroll
        for (int e = 0; e < NEXP; e++) p[e] = fmaf(hv, w[e], p[e]);
    }
    __shared__ float sm[8][NEXP];
    __shared__ int s_last;
#pragma unroll
    for (int e = 0; e < NEXP; e++) {
        float v = p[e];
#pragma unroll
        for (int o = 16; o > 0; o >>= 1) v += __shfl_down_sync(0xffffffffu, v, o);
        if ((threadIdx.x & 31) == 0) sm[threadIdx.x >> 5][e] = v;
    }
    __syncthreads();
    if (threadIdx.x == 0) {
        float best = -1e30f; int bi = 0;
#pragma unroll
        for (int e = 0; e < NEXP; e++) {
            float v = b2[e];
#pragma unroll
            for (int w = 0; w < 8; w++) v += sm[w][e];
            if (v > best) { best = v; bi = e; }   // strict '>' == first-max
        }
        g_expert[t] = bi;
        atomicAdd(&g_counts[bi], 1);
        __threadfence();
        int d = atomicAdd(&g_done, 1);
        s_last = (d == TQ - 1);
    }
    __syncthreads();
    if (s_last) {
        __threadfence();
        if (threadIdx.x == 0) {
            int off = 0, n1 = 0;
            for (int e = 0; e < NEXP; e++) {
                int c = g_counts[e];
                g_offsets[e] = off; off += c;
                for (int r = 0; r < c; r += 128) { g_t1e[n1] = e; g_t1r[n1] = r; n1++; }
            }
            g_nt1 = n1;
        }
        __syncthreads();
        for (int t2 = threadIdx.x; t2 < TQ; t2 += 256) {
            int e = g_expert[t2];
            int pos = g_offsets[e] + atomicAdd(&g_cursor[e], 1);
            g_perm[pos] = t2;
        }
    }
}

// ============ ROUTER GEMM: 3-MMA fp16-split, BK=32 (argmax-critical) ========
__global__ void __launch_bounds__(256, 2)
k_rt(const float* __restrict__ Bw, const float* __restrict__ bias, int N, int K)
{
    extern __shared__ char rawsm[];
    const uint32_t sb = (smem_u32(rawsm) + 1023u) & ~1023u;

    const int tid  = threadIdx.x;
    const int lane = tid & 31;
    const int wid  = tid >> 5;
    const int m_off = (wid >> 1) * 32;
    const int nw    = (wid & 1) * 32;
    const int m0 = blockIdx.x * 128;
    const int n0 = blockIdx.y * 64;

    const int arw = tid >> 1, ah_ = tid & 1;
    const __half* ah_src = g_seqh + (size_t)(m0 + arw) * K;
    const __half* al_src = g_seql + (size_t)(m0 + arw) * K;
    const uint32_t a_hi_dst0 = SWZ((uint32_t)arw * 128 + ah_ * 32);
    const uint32_t a_hi_dst1 = SWZ((uint32_t)arw * 128 + ah_ * 32 + 16);
    const uint32_t a_lo_dst0 = SWZ((uint32_t)arw * 128 + 64 + ah_ * 32);
    const uint32_t a_lo_dst1 = SWZ((uint32_t)arw * 128 + 64 + ah_ * 32 + 16);

    const int bkr_ = tid >> 3, bc8 = (tid & 7) * 8;
    const float* brow = Bw + (size_t)bkr_ * N + n0 + bc8;
    const uint32_t b_sts = SWZ((uint32_t)bkr_ * 128 + bc8 * 2);

    float acc[2][4][4];
    uint32_t corr[2][4][2];
#pragma unroll
    for (int i = 0; i < 2; i++)
#pragma unroll
        for (int j = 0; j < 4; j++) {
#pragma unroll
            for (int q = 0; q < 4; q++) acc[i][j][q] = 0.f;
            corr[i][j][0] = 0u; corr[i][j][1] = 0u;
        }

    const int nch = K >> 5;
    float4 lb[2];

    auto issue_A = [&](int ch, int s) {
        const uint32_t ab = sb + s * RSTAGE;
        const __half* ph = ah_src + ch * 32 + ah_ * 16;
        const __half* pl = al_src + ch * 32 + ah_ * 16;
        cp16(ab + a_hi_dst0, ph);
        cp16(ab + a_hi_dst1, ph + 8);
        cp16(ab + a_lo_dst0, pl);
        cp16(ab + a_lo_dst1, pl + 8);
    };
    auto load_B = [&](int ch) {
        const float* bp = brow + (size_t)(ch * 32) * N;
        lb[0] = *(const float4*)bp;
        lb[1] = *(const float4*)(bp + 4);
    };
    auto store_B = [&](int s) {
        const uint32_t bh = sb + s * RSTAGE + 16384;
        const uint32_t bl = bh + 4096;
        uint32_t h0, h1, h2, h3, l0, l1, l2, l3;
        split2h(lb[0].x, lb[0].y, h0, l0);
        split2h(lb[0].z, lb[0].w, h1, l1);
        split2h(lb[1].x, lb[1].y, h2, l2);
        split2h(lb[1].z, lb[1].w, h3, l3);
        sts128(bh + b_sts, h0, h1, h2, h3);
        sts128(bl + b_sts, l0, l1, l2, l3);
    };
    auto compute = [&](int s) {
        const uint32_t ab = sb + s * RSTAGE;
        const uint32_t bhb = ab + 16384, blb = ab + 20480;
#pragma unroll
        for (int ks = 0; ks < 2; ks++) {
            uint32_t ahf[2][4], alf[2][4];
            const uint32_t acb = (uint32_t)ks * 32 + (lane >> 4) * 16;
            const int arl = lane & 15;
#pragma unroll
            for (int mf = 0; mf < 2; mf++) {
                uint32_t rb = (uint32_t)(m_off + mf * 16 + arl) * 128;
                ldsm4(ahf[mf], ab + SWZ(rb + acb));
                ldsm4(alf[mf], ab + SWZ(rb + 64 + acb));
            }
            uint32_t bhf[4][2], blf[4][2];
            const uint32_t bkr = (uint32_t)(ks * 16 + (lane & 15)) * 128;
#pragma unroll
            for (int g = 0; g < 2; g++) {
                uint32_t cb = (uint32_t)(nw + g * 16 + 8 * (lane >> 4)) * 2;
                uint32_t r[4];
                ldsm4t(r, bhb + SWZ(bkr + cb));
                bhf[2 * g][0] = r[0]; bhf[2 * g][1] = r[1];
                bhf[2 * g + 1][0] = r[2]; bhf[2 * g + 1][1] = r[3];
                ldsm4t(r, blb + SWZ(bkr + cb));
                blf[2 * g][0] = r[0]; blf[2 * g][1] = r[1];
                blf[2 * g + 1][0] = r[2]; blf[2 * g + 1][1] = r[3];
            }
#pragma unroll
            for (int mf = 0; mf < 2; mf++)
#pragma unroll
                for (int nf = 0; nf < 4; nf++) {
                    mma_f32(acc[mf][nf], ahf[mf], bhf[nf][0], bhf[nf][1]);
                    mma_f16(corr[mf][nf], alf[mf], bhf[nf][0], bhf[nf][1]);
                    mma_f16(corr[mf][nf], ahf[mf], blf[nf][0], blf[nf][1]);
                }
        }
    };

    issue_A(0, 0);
    cp_commit();
    load_B(0);
    cp_wait0();
    store_B(0);
    __syncthreads();
    for (int ch = 0; ch < nch; ch++) {
        int s = ch & 1;
        if (ch + 1 < nch) {
            issue_A(ch + 1, s ^ 1);
            cp_commit();
            load_B(ch + 1);
        }
        compute(s);
        if (ch + 1 < nch) store_B(s ^ 1);
        cp_wait0();
        __syncthreads();
    }

    float2 bias2[4];
#pragma unroll
    for (int nf = 0; nf < 4; nf++)
        bias2[nf] = *(const float2*)(bias + n0 + nw + nf * 8 + 2 * (lane & 3));

#pragma unroll
    for (int mf = 0; mf < 2; mf++) {
        int rl = m_off + mf * 16 + (lane >> 2);
#pragma unroll
        for (int half = 0; half < 2; half++) {
            int m = rl + half * 8;
            float* dp = g_h + (size_t)(m0 + m) * N;
#pragma unroll
            for (int nf = 0; nf < 4; nf++) {
                int col = n0 + nw + nf * 8 + 2 * (lane & 3);
                float2 cf = __half22float2(*(__half2*)&corr[mf][nf][half]);
                float x = fmaxf(acc[mf][nf][half * 2 + 0] + cf.x + bias2[nf].x, 0.f);
                float y = fmaxf(acc[mf][nf][half * 2 + 1] + cf.y + bias2[nf].y, 0.f);
                *(float2*)(dp + col) = make_float2(x, y);
            }
        }
    }
}

// ============ EXPERT GEMM: 1-MMA, tile 128x64, BK=64 (R10 config) ===========
// MODE 1: g_hidh[perm] = relu(gather(g_seqh) @ ew1[e] + eb1[e]); K=1024, 1 split
// MODE 2: out[perm[r]] += (g_hidh @ ew2[e]) [+ eb2[e] on split 0]; K=2048/split,
//         blockIdx.z in {0,1}, fp32 atomicAdd epilogue into pre-zeroed d_out.
template <int MODE>
__global__ void __launch_bounds__(256, 2)
k_ex(const float* __restrict__ Bw, const float* __restrict__ bias,
     float* __restrict__ C, int N, int K)
{
    extern __shared__ char rawsm[];
    const uint32_t sb = (smem_u32(rawsm) + 1023u) & ~1023u;

    const int tid  = threadIdx.x;
    const int lane = tid & 31;
    const int wid  = tid >> 5;
    const int m_off = (wid >> 1) * 32;
    const int nw    = (wid & 1) * 32;

    int mt = blockIdx.x;
    if (mt >= g_nt1) return;
    const int e = g_t1e[mt], row0 = g_t1r[mt];
    const int cnt = g_counts[e], goff = g_offsets[e];
    const int kfull = (MODE == 1) ? DDIM : FDIM;
    const int koff  = (MODE == 2) ? (int)blockIdx.z * K : 0;
    const float* Bp = Bw + (size_t)e * kfull * N + (size_t)koff * N;
    const float* biasp = bias + (size_t)e * N;
    const int n0 = blockIdx.y * 64;

    // ---- A loader: row = tid>>1 (0..127), half = tid&1 (32 halfs = 64B)
    const int arw = tid >> 1, ah_ = tid & 1;
    const __half* ah_src;
    {
        int rr = row0 + arw;
        int src = (rr < cnt ? rr : cnt - 1);
        if (MODE == 1) ah_src = g_seqh + (size_t)g_perm[goff + src] * kfull;
        else           ah_src = g_hidh + (size_t)(goff + src) * kfull + koff;
    }
    const uint32_t a_base = (uint32_t)arw * 128 + ah_ * 64;
    const uint32_t a_d0 = SWZ(a_base),      a_d1 = SWZ(a_base + 16);
    const uint32_t a_d2 = SWZ(a_base + 32), a_d3 = SWZ(a_base + 48);

    // ---- B loader: krow = tid>>2 (0..63), quarter = tid&3 -> 16 floats
    const int bkr_ = tid >> 2, bq = (tid & 3) * 16;
    const float* brow = Bp + (size_t)bkr_ * N + n0 + bq;
    const uint32_t b_sts0 = SWZ((uint32_t)bkr_ * 128 + bq * 2);
    const uint32_t b_sts1 = SWZ((uint32_t)bkr_ * 128 + bq * 2 + 16);

    float acc[2][4][4];
#pragma unroll
    for (int i = 0; i < 2; i++)
#pragma unroll
        for (int j = 0; j < 4; j++)
#pragma unroll
            for (int q = 0; q < 4; q++) acc[i][j][q] = 0.f;

    const int nch = K >> 6;
    float4 lb[4];

    auto issue_A = [&](int ch, int s) {
        const uint32_t ab = sb + s * ESTAGE;
        const __half* ph = ah_src + ch * 64 + ah_ * 32;
        cp16(ab + a_d0, ph);
        cp16(ab + a_d1, ph + 8);
        cp16(ab + a_d2, ph + 16);
        cp16(ab + a_d3, ph + 24);
    };
    auto load_B = [&](int ch) {
        const float* bp = brow + (size_t)(ch * 64) * N;
#pragma unroll
        for (int i = 0; i < 4; i++) lb[i] = *(const float4*)(bp + 4 * i);
    };
    auto store_B = [&](int s) {
        const uint32_t bh = sb + s * ESTAGE + 16384;
        uint32_t h[8];
#pragma unroll
        for (int i = 0; i < 4; i++) {
            h[2 * i]     = cvt2h(lb[i].x, lb[i].y);
            h[2 * i + 1] = cvt2h(lb[i].z, lb[i].w);
        }
        sts128(bh + b_sts0, h[0], h[1], h[2], h[3]);
        sts128(bh + b_sts1, h[4], h[5], h[6], h[7]);
    };
    auto compute = [&](int s) {
        const uint32_t ab = sb + s * ESTAGE;
        const uint32_t bhb = ab + 16384;
#pragma unroll
        for (int ks = 0; ks < 4; ks++) {
            uint32_t ahf[2][4];
            const uint32_t acb = (uint32_t)ks * 32 + (lane >> 4) * 16;
            const int arl = lane & 15;
#pragma unroll
            for (int mf = 0; mf < 2; mf++)
                ldsm4(ahf[mf], ab + SWZ((uint32_t)(m_off + mf * 16 + arl) * 128 + acb));
            uint32_t bhf[4][2];
            const uint32_t bkr = (uint32_t)(ks * 16 + (lane & 15)) * 128;
#pragma unroll
            for (int g = 0; g < 2; g++) {
                uint32_t cb = (uint32_t)(nw + g * 16 + 8 * (lane >> 4)) * 2;
                uint32_t r[4];
                ldsm4t(r, bhb + SWZ(bkr + cb));
                bhf[2 * g][0] = r[0]; bhf[2 * g][1] = r[1];
                bhf[2 * g + 1][0] = r[2]; bhf[2 * g + 1][1] = r[3];
            }
#pragma unroll
            for (int mf = 0; mf < 2; mf++)
#pragma unroll
                for (int nf = 0; nf < 4; nf++)
                    mma_f32(acc[mf][nf], ahf[mf], bhf[nf][0], bhf[nf][1]);
        }
    };

    issue_A(0, 0);
    cp_commit();
    load_B(0);
    cp_wait0();
    store_B(0);
    __syncthreads();
    for (int ch = 0; ch < nch; ch++) {
        int s = ch & 1;
        if (ch + 1 < nch) {
            issue_A(ch + 1, s ^ 1);
            cp_commit();
            load_B(ch + 1);
        }
        compute(s);
        if (ch + 1 < nch) store_B(s ^ 1);
        cp_wait0();
        __syncthreads();
    }

    float2 bias2[4];
#pragma unroll
    for (int nf = 0; nf < 4; nf++)
        bias2[nf] = *(const float2*)(biasp + n0 + nw + nf * 8 + 2 * (lane & 3));
    const bool add_bias = (MODE == 1) || (blockIdx.z == 0);

#pragma unroll
    for (int mf = 0; mf < 2; mf++) {
        int rl = m_off + mf * 16 + (lane >> 2);
#pragma unroll
        for (int half = 0; half < 2; half++) {
            int m = rl + half * 8;
            int rr = row0 + m;
            if (rr < cnt) {
                if (MODE == 1) {
                    size_t rowbase = (size_t)(goff + rr) * N;
#pragma unroll
                    for (int nf = 0; nf < 4; nf++) {
                        int col = n0 + nw + nf * 8 + 2 * (lane & 3);
                        float x = fmaxf(acc[mf][nf][half * 2 + 0] + bias2[nf].x, 0.f);
                        float y = fmaxf(acc[mf][nf][half * 2 + 1] + bias2[nf].y, 0.f);
                        *(uint32_t*)(g_hidh + rowbase + col) = cvt2h(x, y);
                    }
                } else {
                    float* dp = C + (size_t)g_perm[goff + rr] * N;
#pragma unroll
                    for (int nf = 0; nf < 4; nf++) {
                        int col = n0 + nw + nf * 8 + 2 * (lane & 3);
                        float x = acc[mf][nf][half * 2 + 0];
                        float y = acc[mf][nf][half * 2 + 1];
                        if (add_bias) { x += bias2[nf].x; y += bias2[nf].y; }
                        atomicAdd(dp + col, x);
                        atomicAdd(dp + col + 1, y);
                    }
                }
            }
        }
    }
}

// ---------------- launch ----------------------------------------------------
extern "C" void kernel_launch(void* const* d_in, const int* in_sizes, int n_in,
                              void* d_out, int out_size) {
    const float* seq = (const float*)d_in[0];
    const float* rw1 = (const float*)d_in[1];
    const float* rb1 = (const float*)d_in[2];
    const float* rw2 = (const float*)d_in[3];
    const float* rb2 = (const float*)d_in[4];
    const float* ew1 = (const float*)d_in[5];
    const float* eb1 = (const float*)d_in[6];
    const float* ew2 = (const float*)d_in[7];
    const float* eb2 = (const float*)d_in[8];
    float* out = (float*)d_out;

    cudaFuncSetAttribute((const void*)k_rt,    cudaFuncAttributeMaxDynamicSharedMemorySize, RSMEM);
    cudaFuncSetAttribute((const void*)k_ex<1>, cudaFuncAttributeMaxDynamicSharedMemorySize, ESMEM);
    cudaFuncSetAttribute((const void*)k_ex<2>, cudaFuncAttributeMaxDynamicSharedMemorySize, ESMEM);

    // Launch #4 = k_ex<1> (profiler window).
    k_cvtA<<<TQ * DDIM / 1024, 256>>>(seq);
    // Router layer 1 (3-MMA split): h = relu(X @ rw1 + rb1)
    k_rt<<<dim3(TQ / 128, DDIM / 64), 256, RSMEM>>>(rw1, rb1, DDIM, DDIM);
    // Router layer 2 + argmax + histogram + (last block) tile list + scatter
    k_router2<<<TQ, 256>>>(rw2, rb2);
    // Expert FFN layer 1 (128x64 tiles, BK=64): hid = relu(X_e @ ew1[e] + eb1[e])
    k_ex<1><<<dim3(MAXT, FDIM / 64), 256, ESMEM>>>(ew1, eb1, nullptr, FDIM, DDIM);
    // Zero output (for the k-split atomic accumulation)
    k_zero<<<TQ * DDIM / 1024, 256>>>(out);
    // Expert FFN layer 2, K split in 2 (blockIdx.z): out += hid @ ew2[e] (+ eb2)
    k_ex<2><<<dim3(MAXT, DDIM / 64, 2), 256, ESMEM>>>(ew2, eb2, out, DDIM, FDIM / 2);
}